// round 3
// baseline (speedup 1.0000x reference)
#include <cuda_runtime.h>
#include <cuda_bf16.h>
#include <math.h>

// ---------------------------------------------------------------------------
// MessageBlock, dst-sorted edge scatter:
//   phi_node = Linear2(silu(Linear1(s)))           (per-NODE)
//   edges counting-sorted by dst; per sorted run, accumulate in registers,
//   flush one atomicAdd set per run (avg degree ~20 -> ~15x less RMW traffic)
// ---------------------------------------------------------------------------

#define F_DIM   128
#define PHI_DIM 384
#define RBF_D   20
#define TILE_M  32
#define KC      16
#define EB      256   // edges staged per batch in edge kernel

typedef unsigned long long ull;

// static scratch (allowed)
__device__ float g_phi[10240 * PHI_DIM];      // per-node phi
__device__ int   g_cnt[16384];                // histogram bins
__device__ int   g_run[16384];                // running offsets (mutated by scatter)
__device__ int   g_perm[262144];              // dst-sorted edge permutation

__device__ __forceinline__ float decode_rc(const int* p) {
    int v = *p;
    if (v > 0 && v < 1000000) return (float)v;   // int32 scalar
    return __uint_as_float((unsigned)v);          // float32 scalar bits
}

// ---- packed f32x2 helpers (sm_103a FFMA2 path) -----------------------------
__device__ __forceinline__ ull pk2(float lo, float hi) {
    ull r; asm("mov.b64 %0, {%1, %2};" : "=l"(r) : "f"(lo), "f"(hi)); return r;
}
__device__ __forceinline__ ull fma2(ull a, ull b, ull c) {
    ull d; asm("fma.rn.f32x2 %0, %1, %2, %3;" : "=l"(d) : "l"(a), "l"(b), "l"(c));
    return d;
}
__device__ __forceinline__ float2 unpk2(ull p) {
    float2 v; asm("mov.b64 {%0, %1}, %2;" : "=f"(v.x), "=f"(v.y) : "l"(p));
    return v;
}

// ---------------------------------------------------------------------------
__global__ void zero_kernel(float* __restrict__ p, int n) {
    int i = (blockIdx.x * blockDim.x + threadIdx.x) * 4;
    if (i + 3 < n) {
        *(float4*)(p + i) = make_float4(0.f, 0.f, 0.f, 0.f);
    } else {
        for (int k = i; k < n; k++) p[k] = 0.f;
    }
}

__global__ void zero_cnt_kernel(int n_bins) {
    int i = blockIdx.x * blockDim.x + threadIdx.x;
    if (i < n_bins) g_cnt[i] = 0;
}

// histogram of dst
__global__ void hist_kernel(const int* __restrict__ edge_idx, int n_edges) {
    for (int e = blockIdx.x * blockDim.x + threadIdx.x; e < n_edges;
         e += gridDim.x * blockDim.x)
        atomicAdd(&g_cnt[edge_idx[e]], 1);
}

// single-block exclusive scan of g_cnt[0..n_bins) -> g_run
__global__ void __launch_bounds__(1024) scan_kernel(int n_bins) {
    __shared__ int part[1024];
    const int tid = threadIdx.x;
    const int per = (n_bins + 1023) / 1024;
    const int base = tid * per;
    int s = 0;
    for (int i = 0; i < per; i++)
        if (base + i < n_bins) s += g_cnt[base + i];
    part[tid] = s;
    __syncthreads();
    // Hillis-Steele inclusive scan
    for (int d = 1; d < 1024; d <<= 1) {
        int v = part[tid];
        int add = (tid >= d) ? part[tid - d] : 0;
        __syncthreads();
        part[tid] = v + add;
        __syncthreads();
    }
    int off = (tid > 0) ? part[tid - 1] : 0;   // exclusive
    for (int i = 0; i < per; i++) {
        if (base + i < n_bins) {
            int c = g_cnt[base + i];
            g_run[base + i] = off;
            off += c;
        }
    }
}

// scatter edge ids into dst-sorted order
__global__ void scatter_kernel(const int* __restrict__ edge_idx, int n_edges) {
    for (int e = blockIdx.x * blockDim.x + threadIdx.x; e < n_edges;
         e += gridDim.x * blockDim.x) {
        int d = edge_idx[e];
        int pos = atomicAdd(&g_run[d], 1);
        g_perm[pos] = e;
    }
}

// ---------------------------------------------------------------------------
// Node MLP: phi = (silu(s @ Ws1^T + bs1)) @ Ws2^T + bs2   -> g_phi [N,384]
// ---------------------------------------------------------------------------
__global__ void __launch_bounds__(256) node_mlp_kernel(
    const float* __restrict__ s,
    const float* __restrict__ Ws1, const float* __restrict__ bs1,
    const float* __restrict__ Ws2, const float* __restrict__ bs2,
    int n_nodes)
{
    __shared__ __align__(16) float s_sm[TILE_M][F_DIM];
    __shared__ __align__(16) float h_sm[TILE_M][F_DIM];
    __shared__ __align__(16) float w_sm[KC][F_DIM + 4];

    const int tid   = threadIdx.x;
    const int m_blk = blockIdx.x * TILE_M;
    const int n0 = (tid & 31) * 4;
    const int m0 = (tid >> 5) * 4;

    for (int i = tid; i < TILE_M * 32; i += 256) {
        int m = i >> 5;
        float4 v = make_float4(0.f, 0.f, 0.f, 0.f);
        if (m_blk + m < n_nodes)
            v = ((const float4*)s)[(size_t)(m_blk + m) * 32 + (i & 31)];
        ((float4*)s_sm)[i] = v;
    }

    ull accp[4][2];

    #pragma unroll
    for (int i = 0; i < 4; i++) { accp[i][0] = 0ull; accp[i][1] = 0ull; }

    for (int kc = 0; kc < F_DIM; kc += KC) {
        __syncthreads();
        for (int i = tid; i < KC * F_DIM; i += 256) {
            int kk = i & (KC - 1);
            int n  = i >> 4;
            w_sm[kk][n] = Ws1[n * F_DIM + kc + kk];
        }
        __syncthreads();
        #pragma unroll
        for (int k4 = 0; k4 < KC; k4 += 4) {
            float a[4][4];
            #pragma unroll
            for (int i = 0; i < 4; i++) {
                float4 t = *(const float4*)&s_sm[m0 + i][kc + k4];
                a[i][0] = t.x; a[i][1] = t.y; a[i][2] = t.z; a[i][3] = t.w;
            }
            #pragma unroll
            for (int kk = 0; kk < 4; kk++) {
                double2 bq = *(const double2*)&w_sm[k4 + kk][n0];
                ull bA = __double_as_longlong(bq.x);
                ull bB = __double_as_longlong(bq.y);
                #pragma unroll
                for (int i = 0; i < 4; i++) {
                    ull aa = pk2(a[i][kk], a[i][kk]);
                    accp[i][0] = fma2(aa, bA, accp[i][0]);
                    accp[i][1] = fma2(aa, bB, accp[i][1]);
                }
            }
        }
    }
    {
        float bb[4];
        #pragma unroll
        for (int j = 0; j < 4; j++) bb[j] = bs1[n0 + j];
        #pragma unroll
        for (int i = 0; i < 4; i++) {
            float2 e0 = unpk2(accp[i][0]);
            float2 e1 = unpk2(accp[i][1]);
            float4 hv; float x;
            x = e0.x + bb[0]; hv.x = x / (1.f + __expf(-x));
            x = e0.y + bb[1]; hv.y = x / (1.f + __expf(-x));
            x = e1.x + bb[2]; hv.z = x / (1.f + __expf(-x));
            x = e1.y + bb[3]; hv.w = x / (1.f + __expf(-x));
            *(float4*)&h_sm[m0 + i][n0] = hv;
        }
    }

    for (int p = 0; p < 3; p++) {
        #pragma unroll
        for (int i = 0; i < 4; i++) { accp[i][0] = 0ull; accp[i][1] = 0ull; }

        const float* W2 = Ws2 + (size_t)p * 128 * F_DIM;
        for (int kc = 0; kc < F_DIM; kc += KC) {
            __syncthreads();
            for (int i = tid; i < KC * F_DIM; i += 256) {
                int kk = i & (KC - 1);
                int n  = i >> 4;
                w_sm[kk][n] = W2[n * F_DIM + kc + kk];
            }
            __syncthreads();
            #pragma unroll
            for (int k4 = 0; k4 < KC; k4 += 4) {
                float a[4][4];
                #pragma unroll
                for (int i = 0; i < 4; i++) {
                    float4 t = *(const float4*)&h_sm[m0 + i][kc + k4];
                    a[i][0] = t.x; a[i][1] = t.y; a[i][2] = t.z; a[i][3] = t.w;
                }
                #pragma unroll
                for (int kk = 0; kk < 4; kk++) {
                    double2 bq = *(const double2*)&w_sm[k4 + kk][n0];
                    ull bA = __double_as_longlong(bq.x);
                    ull bB = __double_as_longlong(bq.y);
                    #pragma unroll
                    for (int i = 0; i < 4; i++) {
                        ull aa = pk2(a[i][kk], a[i][kk]);
                        accp[i][0] = fma2(aa, bA, accp[i][0]);
                        accp[i][1] = fma2(aa, bB, accp[i][1]);
                    }
                }
            }
        }
        float bb[4];
        #pragma unroll
        for (int j = 0; j < 4; j++) bb[j] = bs2[p * 128 + n0 + j];
        #pragma unroll
        for (int i = 0; i < 4; i++) {
            if (m_blk + m0 + i < n_nodes) {
                float2 e0 = unpk2(accp[i][0]);
                float2 e1 = unpk2(accp[i][1]);
                float4 ov = make_float4(e0.x + bb[0], e0.y + bb[1],
                                        e1.x + bb[2], e1.y + bb[3]);
                *(float4*)&g_phi[(size_t)(m_blk + m0 + i) * PHI_DIM + p * 128 + n0] = ov;
            }
        }
    }
}

// ---------------------------------------------------------------------------
// Edge kernel over dst-sorted permutation with run accumulation.
// 128 threads; thread t owns channels {t, t+128, t+256}.
// ---------------------------------------------------------------------------
__global__ void __launch_bounds__(128) edge_kernel(
    const float* __restrict__ vec,
    const float* __restrict__ edge_vector,
    const float* __restrict__ edge_distance,
    const float* __restrict__ edge_rbf,
    const float* __restrict__ Wrbf, const float* __restrict__ brbf,
    const int*   __restrict__ edge_idx,
    float* __restrict__ out_ds, float* __restrict__ out_dvec,
    int n_edges, const int* __restrict__ cutoff_ptr)
{
    __shared__ __align__(16) float rbf_sm[EB * RBF_D];   // 20 KB
    __shared__ float4 geo_sm[EB];                        // 4 KB: vn0,vn1,vn2,fcut
    __shared__ int2   idx_sm[EB];                        // 2 KB: (dst, src)
    __shared__ int    pe_sm[EB];                         // 1 KB

    const int tid = threadIdx.x;
    const float rc     = decode_rc(cutoff_ptr);
    const float inv_rc = 1.0f / rc;

    ull wp0[RBF_D / 2], wp1[RBF_D / 2], wp2[RBF_D / 2];
    #pragma unroll
    for (int q = 0; q < RBF_D / 2; q++) {
        wp0[q] = pk2(Wrbf[(tid      ) * RBF_D + 2 * q], Wrbf[(tid      ) * RBF_D + 2 * q + 1]);
        wp1[q] = pk2(Wrbf[(tid + 128) * RBF_D + 2 * q], Wrbf[(tid + 128) * RBF_D + 2 * q + 1]);
        wp2[q] = pk2(Wrbf[(tid + 256) * RBF_D + 2 * q], Wrbf[(tid + 256) * RBF_D + 2 * q + 1]);
    }
    const float b0 = brbf[tid], b1 = brbf[tid + 128], b2 = brbf[tid + 256];

    const int n_batches = (n_edges + EB - 1) / EB;
    for (int batch = blockIdx.x; batch < n_batches; batch += gridDim.x) {
        const int e0  = batch * EB;
        const int cnt = min(EB, n_edges - e0);

        __syncthreads();
        for (int j = tid; j < cnt; j += 128) pe_sm[j] = g_perm[e0 + j];
        __syncthreads();
        for (int j = tid; j < cnt; j += 128) {
            const int pe = pe_sm[j];
            const float d = edge_distance[pe];
            float fc = 0.5f * (cospif(d * inv_rc) + 1.0f);
            fc = (d < rc) ? fc : 0.0f;
            const float inv_d = 1.0f / d;
            geo_sm[j] = make_float4(edge_vector[pe * 3 + 0] * inv_d,
                                    edge_vector[pe * 3 + 1] * inv_d,
                                    edge_vector[pe * 3 + 2] * inv_d,
                                    fc);
            idx_sm[j] = make_int2(edge_idx[pe],              // dst
                                  edge_idx[n_edges + pe]);   // src
        }
        // rbf rows: 80B per edge, 16B aligned -> 5 x float4 per edge
        {
            const float4* src4 = (const float4*)edge_rbf;
            float4* dst4 = (float4*)rbf_sm;
            const int n4 = cnt * 5;
            for (int i = tid; i < n4; i += 128) {
                int el = i / 5;
                int q  = i - el * 5;
                dst4[i] = src4[(size_t)pe_sm[el] * 5 + q];
            }
        }
        __syncthreads();

        float accS = 0.f, accV0 = 0.f, accV1 = 0.f, accV2 = 0.f;

        #pragma unroll 1
        for (int el = 0; el < cnt; el++) {
            const int2  ii = idx_sm[el];
            const float4 g = geo_sm[el];
            const int src = ii.y;

            const double2* fp = (const double2*)(rbf_sm + el * RBF_D);
            ull acc0 = 0ull, acc1 = 0ull, acc2 = 0ull;
            #pragma unroll
            for (int q = 0; q < 5; q++) {
                double2 f = fp[q];
                ull fA = __double_as_longlong(f.x);
                ull fB = __double_as_longlong(f.y);
                acc0 = fma2(fA, wp0[2 * q], acc0);
                acc1 = fma2(fA, wp1[2 * q], acc1);
                acc2 = fma2(fA, wp2[2 * q], acc2);
                acc0 = fma2(fB, wp0[2 * q + 1], acc0);
                acc1 = fma2(fB, wp1[2 * q + 1], acc1);
                acc2 = fma2(fB, wp2[2 * q + 1], acc2);
            }
            float2 u0 = unpk2(acc0), u1 = unpk2(acc1), u2 = unpk2(acc2);
            const float fc = g.w;
            const float a0 = (u0.x + u0.y + b0) * fc;
            const float a1 = (u1.x + u1.y + b1) * fc;
            const float a2 = (u2.x + u2.y + b2) * fc;

            const float* ph = g_phi + (size_t)src * PHI_DIM;
            const float ws  = __ldg(ph + tid)       * a0;
            const float wvv = __ldg(ph + tid + 128) * a1;
            const float wvs = __ldg(ph + tid + 256) * a2;

            const float* vp = vec + (size_t)src * PHI_DIM;
            accS += ws;
            accV0 += fmaf(wvv, __ldg(vp + tid      ), g.x * wvs);
            accV1 += fmaf(wvv, __ldg(vp + tid + 128), g.y * wvs);
            accV2 += fmaf(wvv, __ldg(vp + tid + 256), g.z * wvs);

            // flush at end of run (dst-sorted => runs contiguous)
            if (el == cnt - 1 || idx_sm[el + 1].x != ii.x) {
                atomicAdd(out_ds + (size_t)ii.x * F_DIM + tid, accS);
                float* op = out_dvec + (size_t)ii.x * PHI_DIM + tid;
                atomicAdd(op,       accV0);
                atomicAdd(op + 128, accV1);
                atomicAdd(op + 256, accV2);
                accS = 0.f; accV0 = 0.f; accV1 = 0.f; accV2 = 0.f;
            }
        }
    }
}

// ---------------------------------------------------------------------------
extern "C" void kernel_launch(void* const* d_in, const int* in_sizes, int n_in,
                              void* d_out, int out_size) {
    const float* s    = (const float*)d_in[0];
    const float* vec  = (const float*)d_in[1];
    const float* ev   = (const float*)d_in[2];
    const float* ed   = (const float*)d_in[3];
    const float* erbf = (const float*)d_in[4];
    const float* Ws1  = (const float*)d_in[5];
    const float* bs1  = (const float*)d_in[6];
    const float* Ws2  = (const float*)d_in[7];
    const float* bs2  = (const float*)d_in[8];
    const float* Wrbf = (const float*)d_in[9];
    const float* brbf = (const float*)d_in[10];
    const int*   eidx = (const int*)d_in[11];
    const int*   rcp  = (const int*)d_in[12];

    const int n_nodes = in_sizes[0] / F_DIM;
    const int n_edges = in_sizes[3];
    float* out_ds   = (float*)d_out;
    float* out_dvec = out_ds + (size_t)n_nodes * F_DIM;

    // 1) zero output + histogram bins
    int zblocks = (out_size / 4 + 255) / 256;
    zero_kernel<<<zblocks, 256>>>((float*)d_out, out_size);
    zero_cnt_kernel<<<(n_nodes + 1023) / 1024, 1024>>>(n_nodes);

    // 2) per-node MLP -> g_phi (independent of sort)
    node_mlp_kernel<<<(n_nodes + TILE_M - 1) / TILE_M, 256>>>(
        s, Ws1, bs1, Ws2, bs2, n_nodes);

    // 3) counting sort by dst
    hist_kernel<<<196, 1024>>>(eidx, n_edges);
    scan_kernel<<<1, 1024>>>(n_nodes);
    scatter_kernel<<<196, 1024>>>(eidx, n_edges);

    // 4) per-edge filter + run-accumulated scatter
    int nb = (n_edges + EB - 1) / EB;
    edge_kernel<<<nb, 128>>>(vec, ev, ed, erbf, Wrbf, brbf, eidx,
                             out_ds, out_dvec, n_edges, rcp);
}

// round 4
// speedup vs baseline: 1.2900x; 1.2900x over previous
#include <cuda_runtime.h>
#include <cuda_bf16.h>
#include <math.h>

// ---------------------------------------------------------------------------
// MessageBlock:
//   phi_node = Linear2(silu(Linear1(s)))           (per-NODE, not per-edge)
//   per edge e: W = (rbf @ Wrbf^T + brbf) * fcut(d)
//               msg = phi_node[src] * W  -> split ws/wvv/wvs
//               ds[dst]   += ws
//               dvec[dst] += wvv*vec[src] + (ev/d) outer wvs
// Edge kernel: software-pipelined gathers (prefetch next edge while computing
// current) — the loop is latency-bound on random phi/vec rows in L2.
// ---------------------------------------------------------------------------

#define F_DIM   128
#define PHI_DIM 384
#define RBF_D   20
#define TILE_M  32
#define KC      16
#define EB      64   // edges staged per batch

typedef unsigned long long ull;

// scratch for per-node phi (15.7 MB), static device allocation (allowed)
__device__ float g_phi[10240 * PHI_DIM];

__device__ __forceinline__ float decode_rc(const int* p) {
    int v = *p;
    if (v > 0 && v < 1000000) return (float)v;   // int32 scalar
    return __uint_as_float((unsigned)v);          // float32 scalar bits
}

// ---- packed f32x2 helpers (sm_103a FFMA2 path) -----------------------------
__device__ __forceinline__ ull pk2(float lo, float hi) {
    ull r; asm("mov.b64 %0, {%1, %2};" : "=l"(r) : "f"(lo), "f"(hi)); return r;
}
__device__ __forceinline__ ull fma2(ull a, ull b, ull c) {
    ull d; asm("fma.rn.f32x2 %0, %1, %2, %3;" : "=l"(d) : "l"(a), "l"(b), "l"(c));
    return d;
}
__device__ __forceinline__ float2 unpk2(ull p) {
    float2 v; asm("mov.b64 {%0, %1}, %2;" : "=f"(v.x), "=f"(v.y) : "l"(p));
    return v;
}

// ---------------------------------------------------------------------------
__global__ void zero_kernel(float* __restrict__ p, int n) {
    int i = (blockIdx.x * blockDim.x + threadIdx.x) * 4;
    if (i + 3 < n) {
        *(float4*)(p + i) = make_float4(0.f, 0.f, 0.f, 0.f);
    } else {
        for (int k = i; k < n; k++) p[k] = 0.f;
    }
}

// ---------------------------------------------------------------------------
// Node MLP: phi = (silu(s @ Ws1^T + bs1)) @ Ws2^T + bs2   -> g_phi [N,384]
// ---------------------------------------------------------------------------
__global__ void __launch_bounds__(256) node_mlp_kernel(
    const float* __restrict__ s,
    const float* __restrict__ Ws1, const float* __restrict__ bs1,
    const float* __restrict__ Ws2, const float* __restrict__ bs2,
    int n_nodes)
{
    __shared__ __align__(16) float s_sm[TILE_M][F_DIM];
    __shared__ __align__(16) float h_sm[TILE_M][F_DIM];
    __shared__ __align__(16) float w_sm[KC][F_DIM + 4];

    const int tid   = threadIdx.x;
    const int m_blk = blockIdx.x * TILE_M;
    const int n0 = (tid & 31) * 4;
    const int m0 = (tid >> 5) * 4;

    for (int i = tid; i < TILE_M * 32; i += 256) {
        int m = i >> 5;
        float4 v = make_float4(0.f, 0.f, 0.f, 0.f);
        if (m_blk + m < n_nodes)
            v = ((const float4*)s)[(size_t)(m_blk + m) * 32 + (i & 31)];
        ((float4*)s_sm)[i] = v;
    }

    ull accp[4][2];

    #pragma unroll
    for (int i = 0; i < 4; i++) { accp[i][0] = 0ull; accp[i][1] = 0ull; }

    for (int kc = 0; kc < F_DIM; kc += KC) {
        __syncthreads();
        for (int i = tid; i < KC * F_DIM; i += 256) {
            int kk = i & (KC - 1);
            int n  = i >> 4;
            w_sm[kk][n] = Ws1[n * F_DIM + kc + kk];
        }
        __syncthreads();
        #pragma unroll
        for (int k4 = 0; k4 < KC; k4 += 4) {
            float a[4][4];
            #pragma unroll
            for (int i = 0; i < 4; i++) {
                float4 t = *(const float4*)&s_sm[m0 + i][kc + k4];
                a[i][0] = t.x; a[i][1] = t.y; a[i][2] = t.z; a[i][3] = t.w;
            }
            #pragma unroll
            for (int kk = 0; kk < 4; kk++) {
                double2 bq = *(const double2*)&w_sm[k4 + kk][n0];
                ull bA = __double_as_longlong(bq.x);
                ull bB = __double_as_longlong(bq.y);
                #pragma unroll
                for (int i = 0; i < 4; i++) {
                    ull aa = pk2(a[i][kk], a[i][kk]);
                    accp[i][0] = fma2(aa, bA, accp[i][0]);
                    accp[i][1] = fma2(aa, bB, accp[i][1]);
                }
            }
        }
    }
    {
        float bb[4];
        #pragma unroll
        for (int j = 0; j < 4; j++) bb[j] = bs1[n0 + j];
        #pragma unroll
        for (int i = 0; i < 4; i++) {
            float2 e0 = unpk2(accp[i][0]);
            float2 e1 = unpk2(accp[i][1]);
            float4 hv; float x;
            x = e0.x + bb[0]; hv.x = x / (1.f + __expf(-x));
            x = e0.y + bb[1]; hv.y = x / (1.f + __expf(-x));
            x = e1.x + bb[2]; hv.z = x / (1.f + __expf(-x));
            x = e1.y + bb[3]; hv.w = x / (1.f + __expf(-x));
            *(float4*)&h_sm[m0 + i][n0] = hv;
        }
    }

    for (int p = 0; p < 3; p++) {
        #pragma unroll
        for (int i = 0; i < 4; i++) { accp[i][0] = 0ull; accp[i][1] = 0ull; }

        const float* W2 = Ws2 + (size_t)p * 128 * F_DIM;
        for (int kc = 0; kc < F_DIM; kc += KC) {
            __syncthreads();
            for (int i = tid; i < KC * F_DIM; i += 256) {
                int kk = i & (KC - 1);
                int n  = i >> 4;
                w_sm[kk][n] = W2[n * F_DIM + kc + kk];
            }
            __syncthreads();
            #pragma unroll
            for (int k4 = 0; k4 < KC; k4 += 4) {
                float a[4][4];
                #pragma unroll
                for (int i = 0; i < 4; i++) {
                    float4 t = *(const float4*)&h_sm[m0 + i][kc + k4];
                    a[i][0] = t.x; a[i][1] = t.y; a[i][2] = t.z; a[i][3] = t.w;
                }
                #pragma unroll
                for (int kk = 0; kk < 4; kk++) {
                    double2 bq = *(const double2*)&w_sm[k4 + kk][n0];
                    ull bA = __double_as_longlong(bq.x);
                    ull bB = __double_as_longlong(bq.y);
                    #pragma unroll
                    for (int i = 0; i < 4; i++) {
                        ull aa = pk2(a[i][kk], a[i][kk]);
                        accp[i][0] = fma2(aa, bA, accp[i][0]);
                        accp[i][1] = fma2(aa, bB, accp[i][1]);
                    }
                }
            }
        }
        float bb[4];
        #pragma unroll
        for (int j = 0; j < 4; j++) bb[j] = bs2[p * 128 + n0 + j];
        #pragma unroll
        for (int i = 0; i < 4; i++) {
            if (m_blk + m0 + i < n_nodes) {
                float2 e0 = unpk2(accp[i][0]);
                float2 e1 = unpk2(accp[i][1]);
                float4 ov = make_float4(e0.x + bb[0], e0.y + bb[1],
                                        e1.x + bb[2], e1.y + bb[3]);
                *(float4*)&g_phi[(size_t)(m_blk + m0 + i) * PHI_DIM + p * 128 + n0] = ov;
            }
        }
    }
}

// ---------------------------------------------------------------------------
// Edge kernel: 128 threads, thread t owns channels {t, t+128, t+256}.
// Software-pipelined: edge el+1's six gathers are issued before edge el's
// rbf dot + atomics, so each warp always has the next edge's loads in flight.
// ---------------------------------------------------------------------------
__global__ void __launch_bounds__(128) edge_kernel(
    const float* __restrict__ vec,
    const float* __restrict__ edge_vector,
    const float* __restrict__ edge_distance,
    const float* __restrict__ edge_rbf,
    const float* __restrict__ Wrbf, const float* __restrict__ brbf,
    const int*   __restrict__ edge_idx,
    float* __restrict__ out_ds, float* __restrict__ out_dvec,
    int n_edges, const int* __restrict__ cutoff_ptr)
{
    __shared__ __align__(16) float rbf_sm[EB * RBF_D];   // 5 KB
    __shared__ float4 geo_sm[EB];                        // vn0,vn1,vn2,fcut
    __shared__ int2   idx_sm[EB];                        // (dst, src)

    const int tid = threadIdx.x;
    const float rc     = decode_rc(cutoff_ptr);
    const float inv_rc = 1.0f / rc;

    ull wp0[RBF_D / 2], wp1[RBF_D / 2], wp2[RBF_D / 2];
    #pragma unroll
    for (int q = 0; q < RBF_D / 2; q++) {
        wp0[q] = pk2(Wrbf[(tid      ) * RBF_D + 2 * q], Wrbf[(tid      ) * RBF_D + 2 * q + 1]);
        wp1[q] = pk2(Wrbf[(tid + 128) * RBF_D + 2 * q], Wrbf[(tid + 128) * RBF_D + 2 * q + 1]);
        wp2[q] = pk2(Wrbf[(tid + 256) * RBF_D + 2 * q], Wrbf[(tid + 256) * RBF_D + 2 * q + 1]);
    }
    const float b0 = brbf[tid], b1 = brbf[tid + 128], b2 = brbf[tid + 256];

    const int e0  = blockIdx.x * EB;
    const int cnt = min(EB, n_edges - e0);

    // stage per-edge metadata
    {
        const float4* src4 = (const float4*)(edge_rbf + (size_t)e0 * RBF_D);
        float4* dst4 = (float4*)rbf_sm;
        const int n4 = cnt * (RBF_D / 4);
        for (int i = tid; i < n4; i += 128) dst4[i] = src4[i];
    }
    if (tid < cnt) {
        const int e = e0 + tid;
        const float d = edge_distance[e];
        float fc = 0.5f * (cospif(d * inv_rc) + 1.0f);
        fc = (d < rc) ? fc : 0.0f;
        const float inv_d = 1.0f / d;
        geo_sm[tid] = make_float4(edge_vector[e * 3 + 0] * inv_d,
                                  edge_vector[e * 3 + 1] * inv_d,
                                  edge_vector[e * 3 + 2] * inv_d,
                                  fc);
        idx_sm[tid] = make_int2(edge_idx[e],              // dst (receiver)
                                edge_idx[n_edges + e]);   // src (sender)
    }
    __syncthreads();

    // ---- software pipeline: prefetch edge 0 ----
    int2   c_ii  = idx_sm[0];
    float4 c_g   = geo_sm[0];
    const float* ph = g_phi + (size_t)c_ii.y * PHI_DIM;
    const float* vp = vec   + (size_t)c_ii.y * PHI_DIM;
    float c_p0 = __ldg(ph + tid);
    float c_p1 = __ldg(ph + tid + 128);
    float c_p2 = __ldg(ph + tid + 256);
    float c_v0 = __ldg(vp + tid);
    float c_v1 = __ldg(vp + tid + 128);
    float c_v2 = __ldg(vp + tid + 256);

    #pragma unroll 2
    for (int el = 0; el < cnt; el++) {
        // issue next edge's gathers FIRST (overlap with this edge's math)
        int2   n_ii; float4 n_g;
        float  n_p0, n_p1, n_p2, n_v0, n_v1, n_v2;
        if (el + 1 < cnt) {
            n_ii = idx_sm[el + 1];
            n_g  = geo_sm[el + 1];
            const float* phn = g_phi + (size_t)n_ii.y * PHI_DIM;
            const float* vpn = vec   + (size_t)n_ii.y * PHI_DIM;
            n_p0 = __ldg(phn + tid);
            n_p1 = __ldg(phn + tid + 128);
            n_p2 = __ldg(phn + tid + 256);
            n_v0 = __ldg(vpn + tid);
            n_v1 = __ldg(vpn + tid + 128);
            n_v2 = __ldg(vpn + tid + 256);
        }

        // rbf dot for current edge (smem, cheap)
        const double2* fp = (const double2*)(rbf_sm + el * RBF_D);
        ull acc0 = 0ull, acc1 = 0ull, acc2 = 0ull;
        #pragma unroll
        for (int q = 0; q < 5; q++) {
            double2 f = fp[q];
            ull fA = __double_as_longlong(f.x);
            ull fB = __double_as_longlong(f.y);
            acc0 = fma2(fA, wp0[2 * q], acc0);
            acc1 = fma2(fA, wp1[2 * q], acc1);
            acc2 = fma2(fA, wp2[2 * q], acc2);
            acc0 = fma2(fB, wp0[2 * q + 1], acc0);
            acc1 = fma2(fB, wp1[2 * q + 1], acc1);
            acc2 = fma2(fB, wp2[2 * q + 1], acc2);
        }
        float2 u0 = unpk2(acc0), u1 = unpk2(acc1), u2 = unpk2(acc2);
        const float fc = c_g.w;
        const float a0 = (u0.x + u0.y + b0) * fc;
        const float a1 = (u1.x + u1.y + b1) * fc;
        const float a2 = (u2.x + u2.y + b2) * fc;

        const float ws  = c_p0 * a0;
        const float wvv = c_p1 * a1;
        const float wvs = c_p2 * a2;

        atomicAdd(out_ds + (size_t)c_ii.x * F_DIM + tid, ws);
        float* op = out_dvec + (size_t)c_ii.x * PHI_DIM + tid;
        atomicAdd(op,       fmaf(wvv, c_v0, c_g.x * wvs));
        atomicAdd(op + 128, fmaf(wvv, c_v1, c_g.y * wvs));
        atomicAdd(op + 256, fmaf(wvv, c_v2, c_g.z * wvs));

        // rotate pipeline
        if (el + 1 < cnt) {
            c_ii = n_ii; c_g = n_g;
            c_p0 = n_p0; c_p1 = n_p1; c_p2 = n_p2;
            c_v0 = n_v0; c_v1 = n_v1; c_v2 = n_v2;
        }
    }
}

// ---------------------------------------------------------------------------
extern "C" void kernel_launch(void* const* d_in, const int* in_sizes, int n_in,
                              void* d_out, int out_size) {
    const float* s    = (const float*)d_in[0];
    const float* vec  = (const float*)d_in[1];
    const float* ev   = (const float*)d_in[2];
    const float* ed   = (const float*)d_in[3];
    const float* erbf = (const float*)d_in[4];
    const float* Ws1  = (const float*)d_in[5];
    const float* bs1  = (const float*)d_in[6];
    const float* Ws2  = (const float*)d_in[7];
    const float* bs2  = (const float*)d_in[8];
    const float* Wrbf = (const float*)d_in[9];
    const float* brbf = (const float*)d_in[10];
    const int*   eidx = (const int*)d_in[11];
    const int*   rcp  = (const int*)d_in[12];

    const int n_nodes = in_sizes[0] / F_DIM;
    const int n_edges = in_sizes[3];
    float* out_ds   = (float*)d_out;
    float* out_dvec = out_ds + (size_t)n_nodes * F_DIM;

    // 1) zero the (poisoned) output
    int zblocks = (out_size / 4 + 255) / 256;
    zero_kernel<<<zblocks, 256>>>((float*)d_out, out_size);

    // 2) per-node MLP -> g_phi
    node_mlp_kernel<<<(n_nodes + TILE_M - 1) / TILE_M, 256>>>(
        s, Ws1, bs1, Ws2, bs2, n_nodes);

    // 3) per-edge filter + scatter (one batch per block)
    int nb = (n_edges + EB - 1) / EB;
    edge_kernel<<<nb, 128>>>(vec, ev, ed, erbf, Wrbf, brbf, eidx,
                             out_ds, out_dvec, n_edges, rcp);
}